// round 17
// baseline (speedup 1.0000x reference)
#include <cuda_runtime.h>
#include <cuda_bf16.h>
#include <cstdint>

// x:   [B=64, C=12, 224, 224] fp32
// w:   [C=12, E=768] fp32
// out: [B=64, P=196, E=768] fp32
//
// CTA = 2x2 patch quad (32x32 px x 12 ch = 48 KB), 192 threads / 6 warps.
// Each warp pools TWO channels: 16 staged independent LDG.128 per thread
// (R7's 8-row full-line pattern, x2 channels) -> 384 lines in flight per SM
// at 4 CTAs/SM. Dual fold per channel -> pooled[12][4]. Phase 2: 12 w-loads
// amortized over FOUR patch outputs, packed f32x2 FFMA epilogue.

#define IMG    224
#define NP     14
#define C_IN   12
#define EMBED  768
#define NTH    192
#define CH_STRIDE ((size_t)IMG * IMG)

using u64t = unsigned long long;

__device__ __forceinline__ u64t ffma2(u64t a, u64t b, u64t c) {
    u64t d;
    asm("fma.rn.f32x2 %0, %1, %2, %3;" : "=l"(d) : "l"(a), "l"(b), "l"(c));
    return d;
}
__device__ __forceinline__ float rsum4(float4 v) {
    return (v.x + v.y) + (v.z + v.w);
}

__global__ __launch_bounds__(NTH, 4) void patch_quad16_kernel(
    const float* __restrict__ x,
    const float* __restrict__ w,
    float* __restrict__ out)
{
    const int pp  = blockIdx.x;        // patch-col pair 0..6
    const int pr  = blockIdx.y;        // patch-row pair 0..6
    const int b   = blockIdx.z;        // 0..63
    const int t   = threadIdx.x;
    const int warp = t >> 5;           // 0..5 -> channels 2w, 2w+1
    const int lane = t & 31;
    const int q8  = lane & 7;          // float4 col within the 32-float row
    const int rh  = lane >> 3;         // row phase 0..3

    // pooled duplicated as (s,s) pairs for the f32x2 epilogue
    __shared__ __align__(16) float2 pooled2[C_IN][4];  // [ch][prow*2+pcol]

    // ---- Phase 1: warp pools 32x32 of channels 2w and 2w+1 ----
    const float* base0 = x
        + (((size_t)(b * C_IN + 2 * warp)) * IMG + (size_t)pr * 32 + rh) * IMG
        + (size_t)pp * 32 + q8 * 4;
    const float* base1 = base0 + CH_STRIDE;

    // 16 independent staged LDG.128 (rows rh+4k, k=0..7, both channels)
    float4 a0 = *reinterpret_cast<const float4*>(base0 + (size_t)(4 * 0) * IMG);
    float4 a1 = *reinterpret_cast<const float4*>(base0 + (size_t)(4 * 1) * IMG);
    float4 a2 = *reinterpret_cast<const float4*>(base0 + (size_t)(4 * 2) * IMG);
    float4 a3 = *reinterpret_cast<const float4*>(base0 + (size_t)(4 * 3) * IMG);
    float4 a4 = *reinterpret_cast<const float4*>(base0 + (size_t)(4 * 4) * IMG);
    float4 a5 = *reinterpret_cast<const float4*>(base0 + (size_t)(4 * 5) * IMG);
    float4 a6 = *reinterpret_cast<const float4*>(base0 + (size_t)(4 * 6) * IMG);
    float4 a7 = *reinterpret_cast<const float4*>(base0 + (size_t)(4 * 7) * IMG);
    float4 c0 = *reinterpret_cast<const float4*>(base1 + (size_t)(4 * 0) * IMG);
    float4 c1 = *reinterpret_cast<const float4*>(base1 + (size_t)(4 * 1) * IMG);
    float4 c2 = *reinterpret_cast<const float4*>(base1 + (size_t)(4 * 2) * IMG);
    float4 c3 = *reinterpret_cast<const float4*>(base1 + (size_t)(4 * 3) * IMG);
    float4 c4 = *reinterpret_cast<const float4*>(base1 + (size_t)(4 * 4) * IMG);
    float4 c5 = *reinterpret_cast<const float4*>(base1 + (size_t)(4 * 5) * IMG);
    float4 c6 = *reinterpret_cast<const float4*>(base1 + (size_t)(4 * 6) * IMG);
    float4 c7 = *reinterpret_cast<const float4*>(base1 + (size_t)(4 * 7) * IMG);

    // channel 0: top (rows 0-15) / bottom (rows 16-31) patch-row sums
    float st0 = (rsum4(a0) + rsum4(a1)) + (rsum4(a2) + rsum4(a3));
    float sb0 = (rsum4(a4) + rsum4(a5)) + (rsum4(a6) + rsum4(a7));
    // channel 1
    float st1 = (rsum4(c0) + rsum4(c1)) + (rsum4(c2) + rsum4(c3));
    float sb1 = (rsum4(c4) + rsum4(c5)) + (rsum4(c6) + rsum4(c7));

    // Fold lane bits 0,1 (cols within patch) and 3,4 (row phases);
    // bit 2 (q8>>2) = patch column survives.
    st0 += __shfl_xor_sync(0xffffffffu, st0, 1);
    sb0 += __shfl_xor_sync(0xffffffffu, sb0, 1);
    st1 += __shfl_xor_sync(0xffffffffu, st1, 1);
    sb1 += __shfl_xor_sync(0xffffffffu, sb1, 1);
    st0 += __shfl_xor_sync(0xffffffffu, st0, 2);
    sb0 += __shfl_xor_sync(0xffffffffu, sb0, 2);
    st1 += __shfl_xor_sync(0xffffffffu, st1, 2);
    sb1 += __shfl_xor_sync(0xffffffffu, sb1, 2);
    st0 += __shfl_xor_sync(0xffffffffu, st0, 8);
    sb0 += __shfl_xor_sync(0xffffffffu, sb0, 8);
    st1 += __shfl_xor_sync(0xffffffffu, st1, 8);
    sb1 += __shfl_xor_sync(0xffffffffu, sb1, 8);
    st0 += __shfl_xor_sync(0xffffffffu, st0, 16);
    sb0 += __shfl_xor_sync(0xffffffffu, sb0, 16);
    st1 += __shfl_xor_sync(0xffffffffu, st1, 16);
    sb1 += __shfl_xor_sync(0xffffffffu, sb1, 16);

    if ((lane & 27) == 0) {            // lanes 0 and 4
        const int pc = (lane >> 2) & 1;
        pooled2[2 * warp + 0][0 + pc] = make_float2(st0, st0);
        pooled2[2 * warp + 0][2 + pc] = make_float2(sb0, sb0);
        pooled2[2 * warp + 1][0 + pc] = make_float2(st1, st1);
        pooled2[2 * warp + 1][2 + pc] = make_float2(sb1, sb1);
    }
    __syncthreads();

    // ---- Phase 2: 12 w-loads serve FOUR patch outputs (f32x2) ----
    const int e4 = t;                  // float4 slot 0..191
    u64t A0 = 0, A1 = 0;               // patch (0,0): (e,e+1),(e+2,e+3)
    u64t B0 = 0, B1 = 0;               // patch (0,1)
    u64t C0 = 0, C1 = 0;               // patch (1,0)
    u64t D0 = 0, D1 = 0;               // patch (1,1)
    #pragma unroll
    for (int c = 0; c < C_IN; ++c) {
        const ulonglong2 wv =
            *reinterpret_cast<const ulonglong2*>(&w[c * EMBED + e4 * 4]);
        const u64t p0 = *reinterpret_cast<const u64t*>(&pooled2[c][0]);
        const u64t p1 = *reinterpret_cast<const u64t*>(&pooled2[c][1]);
        const u64t p2 = *reinterpret_cast<const u64t*>(&pooled2[c][2]);
        const u64t p3 = *reinterpret_cast<const u64t*>(&pooled2[c][3]);
        A0 = ffma2(p0, wv.x, A0);  A1 = ffma2(p0, wv.y, A1);
        B0 = ffma2(p1, wv.x, B0);  B1 = ffma2(p1, wv.y, B1);
        C0 = ffma2(p2, wv.x, C0);  C1 = ffma2(p2, wv.y, C1);
        D0 = ffma2(p3, wv.x, D0);  D1 = ffma2(p3, wv.y, D1);
    }

    const int pi = pr * 2;             // top patch row
    const int pj = pp * 2;             // left patch col
    float* o = out + ((size_t)b * (NP * NP) + (size_t)pi * NP + pj) * EMBED + e4 * 4;
    ulonglong2 rA; rA.x = A0; rA.y = A1;
    ulonglong2 rB; rB.x = B0; rB.y = B1;
    ulonglong2 rC; rC.x = C0; rC.y = C1;
    ulonglong2 rD; rD.x = D0; rD.y = D1;
    *reinterpret_cast<ulonglong2*>(o)                          = rA; // (pi,  pj)
    *reinterpret_cast<ulonglong2*>(o + EMBED)                  = rB; // (pi,  pj+1)
    *reinterpret_cast<ulonglong2*>(o + (size_t)NP * EMBED)     = rC; // (pi+1,pj)
    *reinterpret_cast<ulonglong2*>(o + (size_t)(NP + 1) * EMBED) = rD; // (pi+1,pj+1)
}

extern "C" void kernel_launch(void* const* d_in, const int* in_sizes, int n_in,
                              void* d_out, int out_size)
{
    const float* x = (const float*)d_in[0];
    const float* w = (const float*)d_in[1];
    float* out = (float*)d_out;

    dim3 grid(7, 7, 64);   // 3136 CTAs
    patch_quad16_kernel<<<grid, NTH>>>(x, w, out);
}